// round 10
// baseline (speedup 1.0000x reference)
#include <cuda_runtime.h>
#include <cuda_fp16.h>
#include <cstdint>

#define NN 50000
#define EE 800000
#define NBLK 196   // ceil(NN/256)

// ---------------- device scratch (all-fp16 activation pipeline) ----------------
__device__ __half g_x16[NN * 128];    // x mirror; reused as layer-3 proj p16 [NN*64]
__device__ __half g_hA16[NN * 128];   // layer-1 activations
__device__ __half g_hB16[NN * 128];   // layer-2 activations
__device__ __half g_n16[NN * 128];    // aggregated neighbor features
__device__ float  g_self[NN * 64];    // layer-3 self projection (fp32)
__device__ int   g_deg[NN];
__device__ int   g_off[NN + 1];
__device__ int   g_cur[NN];
__device__ int   g_csr[EE];
__device__ int   g_bsum[256];
__device__ int   g_boff[256];
__device__ __half g_B16[3 * 128 * 256]; // transposed fp16 weights, 3 layers

// ---------------- helpers ----------------
__device__ __forceinline__ uint32_t smem_u32(const void* p) {
    uint32_t a;
    asm("{ .reg .u64 t; cvta.to.shared.u64 t, %1; cvt.u32.u64 %0, t; }" : "=r"(a) : "l"(p));
    return a;
}
__device__ __forceinline__ void mma_f16(float* d, const uint32_t* a, const uint32_t* b) {
    asm volatile(
        "mma.sync.aligned.m16n8k16.row.col.f32.f16.f16.f32 "
        "{%0,%1,%2,%3}, {%4,%5,%6,%7}, {%8,%9}, {%0,%1,%2,%3};"
        : "+f"(d[0]), "+f"(d[1]), "+f"(d[2]), "+f"(d[3])
        : "r"(a[0]), "r"(a[1]), "r"(a[2]), "r"(a[3]), "r"(b[0]), "r"(b[1]));
}
__device__ __forceinline__ void ldsm_x4(uint32_t* r, uint32_t addr) {
    asm volatile("ldmatrix.sync.aligned.m8n8.x4.shared.b16 {%0,%1,%2,%3}, [%4];"
                 : "=r"(r[0]), "=r"(r[1]), "=r"(r[2]), "=r"(r[3]) : "r"(addr));
}

// ---------------- setup: x->fp16 mirror + all 3 weight sets -> transposed fp16 ----------------
// items [0, NCONV4): conv float4 -> half2x2
// items [NCONV4, NCONV4+81920): weight prep
#define NCONV4 (NN * 32)
__global__ void setup_kernel(const float4* __restrict__ x4, uint2* __restrict__ x16,
                             const float* __restrict__ Ws1, const float* __restrict__ Wn1,
                             const float* __restrict__ Ws2, const float* __restrict__ Wn2,
                             const float* __restrict__ Ws3, const float* __restrict__ Wn3,
                             __half* __restrict__ B16) {
    int idx = blockIdx.x * blockDim.x + threadIdx.x;
    if (idx < NCONV4) {
        float4 v = x4[idx];
        __half2 h0 = __floats2half2_rn(v.x, v.y);
        __half2 h1 = __floats2half2_rn(v.z, v.w);
        x16[idx] = make_uint2(*reinterpret_cast<uint32_t*>(&h0), *reinterpret_cast<uint32_t*>(&h1));
        return;
    }
    int w = idx - NCONV4;
    if (w < 2 * 128 * 256) {
        int layer = w >> 15;
        int li = w & 32767;
        int n = li >> 8, k = li & 255;
        const float* W1 = layer ? Ws2 : Ws1;
        const float* W2 = layer ? Wn2 : Wn1;
        float wv = (k < 128) ? W1[k * 128 + n] : W2[(k - 128) * 128 + n];
        B16[w] = __float2half_rn(wv);
    } else if (w < 2 * 128 * 256 + 128 * 128) {
        int li = w - 2 * 128 * 256;
        int n = li >> 7, k = li & 127;
        float wv = (n < 64) ? Ws3[k * 64 + n] : Wn3[k * 64 + (n - 64)];
        B16[2 * 128 * 256 + n * 128 + k] = __float2half_rn(wv);
    }
}

// ---------------- CSR build (vectorized: 4 edges/thread) ----------------
__global__ void count4_kernel(const int4* __restrict__ dst4) {
    int i = blockIdx.x * blockDim.x + threadIdx.x;
    if (i < EE / 4) {
        int4 d = dst4[i];
        atomicAdd(&g_deg[d.x], 1);
        atomicAdd(&g_deg[d.y], 1);
        atomicAdd(&g_deg[d.z], 1);
        atomicAdd(&g_deg[d.w], 1);
    }
}
__global__ void scan_partials() {
    __shared__ int sh[256];
    int t = threadIdx.x;
    int i = blockIdx.x * 256 + t;
    sh[t] = (i < NN) ? g_deg[i] : 0;
    __syncthreads();
    for (int o = 128; o > 0; o >>= 1) {
        if (t < o) sh[t] += sh[t + o];
        __syncthreads();
    }
    if (t == 0) g_bsum[blockIdx.x] = sh[0];
}
__global__ void scan_bsums() {
    __shared__ int sh[256];
    int t = threadIdx.x;
    int v = (t < NBLK) ? g_bsum[t] : 0;
    sh[t] = v;
    __syncthreads();
    for (int o = 1; o < 256; o <<= 1) {
        int x = (t >= o) ? sh[t - o] : 0;
        __syncthreads();
        sh[t] += x;
        __syncthreads();
    }
    if (t < NBLK) g_boff[t] = sh[t] - v;   // exclusive
}
__global__ void scan_final() {
    __shared__ int sh[256];
    int t = threadIdx.x;
    int i = blockIdx.x * 256 + t;
    int v = (i < NN) ? g_deg[i] : 0;
    sh[t] = v;
    __syncthreads();
    for (int o = 1; o < 256; o <<= 1) {
        int x = (t >= o) ? sh[t - o] : 0;
        __syncthreads();
        sh[t] += x;
        __syncthreads();
    }
    int off = g_boff[blockIdx.x] + sh[t] - v;   // exclusive
    if (i <= NN) g_off[i] = off;
    if (i < NN) g_cur[i] = off;                  // fill bumps this directly
}
__global__ void fill4_kernel(const int4* __restrict__ src4, const int4* __restrict__ dst4) {
    int i = blockIdx.x * blockDim.x + threadIdx.x;
    if (i < EE / 4) {
        int4 d = dst4[i];
        int4 s = src4[i];
        int p0 = atomicAdd(&g_cur[d.x], 1);
        int p1 = atomicAdd(&g_cur[d.y], 1);
        int p2 = atomicAdd(&g_cur[d.z], 1);
        int p3 = atomicAdd(&g_cur[d.w], 1);
        g_csr[p0] = s.x;
        g_csr[p1] = s.y;
        g_csr[p2] = s.z;
        g_csr[p3] = s.w;
    }
}

// ---------------- mean aggregation (128-dim): warp per node, fp16 in/out ----------------
__global__ void agg16_kernel(const __half* __restrict__ h16, __half* __restrict__ n16) {
    int gt = blockIdx.x * blockDim.x + threadIdx.x;
    int node = gt >> 5;
    int lane = gt & 31;
    if (node >= NN) return;
    int s = g_off[node], e = g_off[node + 1];
    float a0 = 0.f, a1 = 0.f, a2 = 0.f, a3 = 0.f;
    int j = s;
    for (; j + 4 <= e; j += 4) {
        int i0 = g_csr[j], i1 = g_csr[j + 1], i2 = g_csr[j + 2], i3 = g_csr[j + 3];
        uint2 v0 = *reinterpret_cast<const uint2*>(h16 + (size_t)i0 * 128 + lane * 4);
        uint2 v1 = *reinterpret_cast<const uint2*>(h16 + (size_t)i1 * 128 + lane * 4);
        uint2 v2 = *reinterpret_cast<const uint2*>(h16 + (size_t)i2 * 128 + lane * 4);
        uint2 v3 = *reinterpret_cast<const uint2*>(h16 + (size_t)i3 * 128 + lane * 4);
        float2 f;
        f = __half22float2(*reinterpret_cast<__half2*>(&v0.x)); a0 += f.x; a1 += f.y;
        f = __half22float2(*reinterpret_cast<__half2*>(&v0.y)); a2 += f.x; a3 += f.y;
        f = __half22float2(*reinterpret_cast<__half2*>(&v1.x)); a0 += f.x; a1 += f.y;
        f = __half22float2(*reinterpret_cast<__half2*>(&v1.y)); a2 += f.x; a3 += f.y;
        f = __half22float2(*reinterpret_cast<__half2*>(&v2.x)); a0 += f.x; a1 += f.y;
        f = __half22float2(*reinterpret_cast<__half2*>(&v2.y)); a2 += f.x; a3 += f.y;
        f = __half22float2(*reinterpret_cast<__half2*>(&v3.x)); a0 += f.x; a1 += f.y;
        f = __half22float2(*reinterpret_cast<__half2*>(&v3.y)); a2 += f.x; a3 += f.y;
    }
    for (; j < e; j++) {
        int sidx = g_csr[j];
        uint2 v = *reinterpret_cast<const uint2*>(h16 + (size_t)sidx * 128 + lane * 4);
        float2 f0 = __half22float2(*reinterpret_cast<__half2*>(&v.x));
        float2 f1 = __half22float2(*reinterpret_cast<__half2*>(&v.y));
        a0 += f0.x; a1 += f0.y; a2 += f1.x; a3 += f1.y;
    }
    float inv = 1.0f / (float)max(e - s, 1);
    __half2 o0 = __floats2half2_rn(a0 * inv, a1 * inv);
    __half2 o1 = __floats2half2_rn(a2 * inv, a3 * inv);
    *reinterpret_cast<uint2*>(n16 + (size_t)node * 128 + lane * 4) =
        make_uint2(*reinterpret_cast<uint32_t*>(&o0), *reinterpret_cast<uint32_t*>(&o1));
}

// ---------------- layer-3 final: out = self + mean(proj16[src]) ----------------
__global__ void agg3_kernel(const __half* __restrict__ p16, const float* __restrict__ self,
                            float* __restrict__ out) {
    int gt = blockIdx.x * blockDim.x + threadIdx.x;
    int node = gt >> 5;
    int lane = gt & 31;
    if (node >= NN) return;
    int s = g_off[node], e = g_off[node + 1];
    float a0 = 0.f, a1 = 0.f;
    int j = s;
    for (; j + 4 <= e; j += 4) {
        int i0 = g_csr[j], i1 = g_csr[j + 1], i2 = g_csr[j + 2], i3 = g_csr[j + 3];
        uint32_t v0 = *reinterpret_cast<const uint32_t*>(p16 + (size_t)i0 * 64 + lane * 2);
        uint32_t v1 = *reinterpret_cast<const uint32_t*>(p16 + (size_t)i1 * 64 + lane * 2);
        uint32_t v2 = *reinterpret_cast<const uint32_t*>(p16 + (size_t)i2 * 64 + lane * 2);
        uint32_t v3 = *reinterpret_cast<const uint32_t*>(p16 + (size_t)i3 * 64 + lane * 2);
        float2 f;
        f = __half22float2(*reinterpret_cast<__half2*>(&v0)); a0 += f.x; a1 += f.y;
        f = __half22float2(*reinterpret_cast<__half2*>(&v1)); a0 += f.x; a1 += f.y;
        f = __half22float2(*reinterpret_cast<__half2*>(&v2)); a0 += f.x; a1 += f.y;
        f = __half22float2(*reinterpret_cast<__half2*>(&v3)); a0 += f.x; a1 += f.y;
    }
    for (; j < e; j++) {
        int sidx = g_csr[j];
        uint32_t v = *reinterpret_cast<const uint32_t*>(p16 + (size_t)sidx * 64 + lane * 2);
        float2 f = __half22float2(*reinterpret_cast<__half2*>(&v));
        a0 += f.x; a1 += f.y;
    }
    float inv = 1.0f / (float)max(e - s, 1);
    float2 sv = *reinterpret_cast<const float2*>(self + (size_t)node * 64 + lane * 2);
    *reinterpret_cast<float2*>(out + (size_t)node * 64 + lane * 2) =
        make_float2(sv.x + a0 * inv, sv.y + a1 * inv);
}

// ---------------- single-pass fp16 tensor-core GEMM (fp32 accum) ----------------
// MODE 0: relu*mask epilogue, fp16 128-wide output (layers 1,2)
// MODE 2: layer-3 split: cols<64 -> self fp32 (+bias), cols>=64 -> p16 fp16 (no bias)
template <int KCHUNKS, bool DUAL, int MODE>
__global__ void __launch_bounds__(256, 2)
sage_mma_kernel(const __half* __restrict__ A0, const __half* __restrict__ A1,
                const __half* __restrict__ B16,
                const float* __restrict__ bias, const float* __restrict__ mask,
                float* __restrict__ out, __half* __restrict__ h16out) {
    constexpr int PAD = 40;                 // halves per smem row (80B: conflict-free ldmatrix)
    constexpr int KTOT = KCHUNKS * 32;
    constexpr int BUFH = 128 * PAD;
    extern __shared__ uint16_t sm[];
    const uint32_t base = smem_u32(sm);
    uint16_t* sA = sm;                      // [2][128][PAD]
    uint16_t* sB = sm + 2 * BUFH;           // [2][128][PAD]

    const int tid = threadIdx.x, lane = tid & 31, wid = tid >> 5;
    const int bm = blockIdx.x * 128;
    const int wm = (wid & 3) * 32;          // 4 warps down M
    const int wn = (wid >> 2) * 64;         // 2 warps across N

    float acc[2][8][4];
#pragma unroll
    for (int m = 0; m < 2; m++)
#pragma unroll
        for (int n = 0; n < 8; n++)
#pragma unroll
            for (int i = 0; i < 4; i++) acc[m][n][i] = 0.f;

    uint4 pa[2], pb[2];
    auto loadAB = [&](int ch) {
        const __half* asrc = DUAL ? (ch < KCHUNKS / 2 ? A0 : A1) : A0;
        int klocal = DUAL ? (ch & (KCHUNKS / 2 - 1)) * 32 : ch * 32;
        int k0 = ch * 32;
#pragma unroll
        for (int j = 0; j < 2; j++) {
            int item = tid + j * 256;
            int row = item >> 2, q = item & 3;
            int grow = bm + row;
            pa[j] = (grow < NN)
                ? *reinterpret_cast<const uint4*>(asrc + (size_t)grow * 128 + klocal + q * 8)
                : make_uint4(0, 0, 0, 0);
            pb[j] = *reinterpret_cast<const uint4*>(B16 + row * KTOT + k0 + q * 8);
        }
    };
    auto storeAB = [&](int buf) {
#pragma unroll
        for (int j = 0; j < 2; j++) {
            int item = tid + j * 256;
            int row = item >> 2, q = item & 3;
            int off = buf * BUFH + row * PAD + q * 8;
            *reinterpret_cast<uint4*>(&sA[off]) = pa[j];
            *reinterpret_cast<uint4*>(&sB[off]) = pb[j];
        }
    };

    loadAB(0);
    storeAB(0);

    for (int ch = 0; ch < KCHUNKS; ch++) {
        __syncthreads();
        int buf = ch & 1;
        bool more = (ch + 1 < KCHUNKS);
        if (more) loadAB(ch + 1);   // LDGs in flight during MMA work

#pragma unroll
        for (int ks = 0; ks < 2; ks++) {
            uint32_t ah[2][4];
            int arow = wm + (lane & 7) + ((lane >> 3) & 1) * 8;
            int acol = ks * 16 + (lane >> 4) * 8;
#pragma unroll
            for (int m = 0; m < 2; m++) {
                uint32_t aoff = (uint32_t)(buf * BUFH + (arow + m * 16) * PAD + acol) * 2;
                ldsm_x4(ah[m], base + aoff);
            }
            int brow = wn + (lane & 7) + ((lane >> 4) & 1) * 8;
            int bcol = ks * 16 + ((lane >> 3) & 1) * 8;
#pragma unroll
            for (int nt2 = 0; nt2 < 4; nt2++) {
                uint32_t bh[4];
                uint32_t boff = (uint32_t)((2 + buf) * BUFH + (brow + nt2 * 16) * PAD + bcol) * 2;
                ldsm_x4(bh, base + boff);
#pragma unroll
                for (int m = 0; m < 2; m++) {
                    mma_f16(acc[m][nt2 * 2], ah[m], &bh[0]);
                    mma_f16(acc[m][nt2 * 2 + 1], ah[m], &bh[2]);
                }
            }
        }
        if (more) storeAB(buf ^ 1);
    }

    // ---- epilogue ----
#pragma unroll
    for (int m = 0; m < 2; m++) {
        int r0 = bm + wm + m * 16 + (lane >> 2);
#pragma unroll
        for (int nt = 0; nt < 8; nt++) {
            int c = wn + nt * 8 + (lane & 3) * 2;
#pragma unroll
            for (int hh = 0; hh < 2; hh++) {
                int r = r0 + hh * 8;
                if (r >= NN) continue;
                float v0 = acc[m][nt][hh * 2 + 0];
                float v1 = acc[m][nt][hh * 2 + 1];
                if (MODE == 0) {
                    v0 += bias[c];
                    v1 += bias[c + 1];
                    float2 mv = *reinterpret_cast<const float2*>(mask + (size_t)r * 128 + c);
                    v0 = fmaxf(v0, 0.f) * mv.x;
                    v1 = fmaxf(v1, 0.f) * mv.y;
                    *reinterpret_cast<__half2*>(h16out + (size_t)r * 128 + c) =
                        __floats2half2_rn(v0, v1);
                } else {
                    if (c < 64) {
                        v0 += bias[c];
                        v1 += bias[c + 1];
                        *reinterpret_cast<float2*>(out + (size_t)r * 64 + c) = make_float2(v0, v1);
                    } else {
                        *reinterpret_cast<__half2*>(h16out + (size_t)r * 64 + (c - 64)) =
                            __floats2half2_rn(v0, v1);
                    }
                }
            }
        }
    }
}

// ---------------- launch ----------------
extern "C" void kernel_launch(void* const* d_in, const int* in_sizes, int n_in,
                              void* d_out, int out_size) {
    const float* x   = (const float*)d_in[0];
    const int*   src = (const int*)d_in[1];
    const int*   dst = (const int*)d_in[2];
    const float* Ws1 = (const float*)d_in[3];
    const float* Wn1 = (const float*)d_in[4];
    const float* b1  = (const float*)d_in[5];
    const float* Ws2 = (const float*)d_in[6];
    const float* Wn2 = (const float*)d_in[7];
    const float* b2  = (const float*)d_in[8];
    const float* Ws3 = (const float*)d_in[9];
    const float* Wn3 = (const float*)d_in[10];
    const float* b3  = (const float*)d_in[11];
    const float* m1  = (const float*)d_in[12];
    const float* m2  = (const float*)d_in[13];
    float* out = (float*)d_out;

    // Real DEVICE addresses (host symbol = ATS shadow trap, see R1)
    __half *x16 = nullptr, *hA16 = nullptr, *hB16 = nullptr, *n16 = nullptr, *B16 = nullptr;
    float* selfp = nullptr;
    int* degp = nullptr;
    cudaGetSymbolAddress((void**)&x16, g_x16);
    cudaGetSymbolAddress((void**)&hA16, g_hA16);
    cudaGetSymbolAddress((void**)&hB16, g_hB16);
    cudaGetSymbolAddress((void**)&n16, g_n16);
    cudaGetSymbolAddress((void**)&B16, g_B16);
    cudaGetSymbolAddress((void**)&selfp, g_self);
    cudaGetSymbolAddress((void**)&degp, g_deg);

    constexpr int SMEM_GEMM = 4 * 128 * 40 * 2;  // 40960 B
    cudaFuncSetAttribute(sage_mma_kernel<8, true, 0>,
                         cudaFuncAttributeMaxDynamicSharedMemorySize, SMEM_GEMM);
    cudaFuncSetAttribute(sage_mma_kernel<4, false, 2>,
                         cudaFuncAttributeMaxDynamicSharedMemorySize, SMEM_GEMM);

    // ---- setup: conv + weight prep in one kernel; deg zero via memset node ----
    setup_kernel<<<(NCONV4 + 81920 + 255) / 256, 256>>>((const float4*)x, (uint2*)x16,
                                                        Ws1, Wn1, Ws2, Wn2, Ws3, Wn3, B16);
    cudaMemsetAsync(degp, 0, NN * sizeof(int));

    // ---- CSR build (4 edges/thread) ----
    count4_kernel<<<(EE / 4 + 255) / 256, 256>>>((const int4*)dst);
    scan_partials<<<NBLK, 256>>>();
    scan_bsums<<<1, 256>>>();
    scan_final<<<NBLK, 256>>>();
    fill4_kernel<<<(EE / 4 + 255) / 256, 256>>>((const int4*)src, (const int4*)dst);

    int tiles = (NN + 127) / 128;            // 391
    int aggBlocks = (NN * 32 + 255) / 256;

    // ---- layer 1 ----
    agg16_kernel<<<aggBlocks, 256>>>(x16, n16);
    sage_mma_kernel<8, true, 0><<<tiles, 256, SMEM_GEMM>>>(x16, n16, B16, b1, m1, nullptr, hA16);

    // ---- layer 2 ----
    agg16_kernel<<<aggBlocks, 256>>>(hA16, n16);
    sage_mma_kernel<8, true, 0><<<tiles, 256, SMEM_GEMM>>>(hA16, n16, B16 + 32768, b2, m2, nullptr, hB16);

    // ---- layer 3: project (self fp32, proj fp16 into x16), then aggregate ----
    sage_mma_kernel<4, false, 2><<<tiles, 256, SMEM_GEMM>>>(hB16, nullptr, B16 + 65536, b3, nullptr, selfp, x16);
    agg3_kernel<<<aggBlocks, 256>>>(x16, selfp, out);
}